// round 1
// baseline (speedup 1.0000x reference)
#include <cuda_runtime.h>
#include <cuda_bf16.h>
#include <math.h>

// Problem constants (from reference)
#define NN 50000
#define EE 800000
#define HH 128
#define BN_EPS 1e-5f

// Scratch (device globals; no allocation allowed)
__device__ float g_deg[NN];
__device__ float g_dinv[NN];
__device__ float g_xw[(size_t)NN * HH];   // GEMM output / messages
__device__ float g_agg[(size_t)NN * HH];  // aggregation accumulator
__device__ float g_h[(size_t)NN * HH];    // layer activations
__device__ float g_A[(size_t)NN * HH];    // h @ epW1[:H]
__device__ float g_B[(size_t)NN * HH];    // h @ epW1[H:]

// ---------------- degree / normalization ----------------
__global__ void k_deg_init() {
    int i = blockIdx.x * blockDim.x + threadIdx.x;
    if (i < NN) g_deg[i] = 1.0f;  // self loop
}

__global__ void k_deg_acc(const int* __restrict__ dst) {
    int e = blockIdx.x * blockDim.x + threadIdx.x;
    if (e < EE) atomicAdd(&g_deg[dst[e]], 1.0f);
}

__global__ void k_dinv() {
    int i = blockIdx.x * blockDim.x + threadIdx.x;
    if (i < NN) g_dinv[i] = rsqrtf(g_deg[i]);
}

// ---------------- GEMM: Y[nrows,128] = X[nrows,128] @ W[128,128] ----------------
// 64-row tile per block, 256 threads, 8x4 register tile per thread.
__global__ void k_gemm128(const float* __restrict__ X, const float* __restrict__ W,
                          float* __restrict__ Y, int nrows) {
    __shared__ __align__(16) float sX[64][32];
    __shared__ __align__(16) float sW[32][128];
    int t = threadIdx.x;
    int r0 = blockIdx.x * 64;
    int cg = t & 31;   // cols cg*4 .. cg*4+3
    int rg = t >> 5;   // rows rg*8 .. rg*8+7

    float acc[8][4];
#pragma unroll
    for (int i = 0; i < 8; i++)
#pragma unroll
        for (int j = 0; j < 4; j++) acc[i][j] = 0.f;

    for (int kk = 0; kk < 128; kk += 32) {
#pragma unroll
        for (int p = 0; p < 8; p++) {  // 64*32 / 256 = 8 elems per thread
            int i = t + p * 256;
            int r = i >> 5, c = i & 31;
            int gr = r0 + r;
            sX[r][c] = (gr < nrows) ? X[(size_t)gr * 128 + kk + c] : 0.f;
        }
#pragma unroll
        for (int p = 0; p < 16; p++) {  // 32*128 / 256 = 16 elems per thread
            int i = t + p * 256;
            int k = i >> 7, c = i & 127;
            sW[k][c] = W[(size_t)(kk + k) * 128 + c];
        }
        __syncthreads();
#pragma unroll
        for (int k = 0; k < 32; k++) {
            float4 b = *(const float4*)&sW[k][cg * 4];
#pragma unroll
            for (int i = 0; i < 8; i++) {
                float a = sX[rg * 8 + i][k];
                acc[i][0] += a * b.x;
                acc[i][1] += a * b.y;
                acc[i][2] += a * b.z;
                acc[i][3] += a * b.w;
            }
        }
        __syncthreads();
    }
#pragma unroll
    for (int i = 0; i < 8; i++) {
        int gr = r0 + rg * 8 + i;
        if (gr < nrows) {
            float4 v = make_float4(acc[i][0], acc[i][1], acc[i][2], acc[i][3]);
            *(float4*)&Y[(size_t)gr * 128 + cg * 4] = v;
        }
    }
}

// ---------------- self-loop init: agg[n] = dinv[n]^2 * xw[n] ----------------
__global__ void k_selfinit() {
    int i = blockIdx.x * blockDim.x + threadIdx.x;  // float4 units
    if (i < NN * (HH / 4)) {
        int n = i >> 5;
        float di = g_dinv[n];
        float c = di * di;
        float4 v = ((const float4*)g_xw)[i];
        v.x *= c; v.y *= c; v.z *= c; v.w *= c;
        ((float4*)g_agg)[i] = v;
    }
}

// ---------------- edge scatter: agg[dst] += dinv[s]*dinv[d] * xw[src] ----------------
// One warp per edge, one float4 vectorized reduction per lane.
__global__ void k_scatter(const int* __restrict__ src, const int* __restrict__ dst) {
    int gt = blockIdx.x * blockDim.x + threadIdx.x;
    int e = gt >> 5;
    int lane = gt & 31;
    if (e >= EE) return;
    int s = src[e], d = dst[e];
    float coef = g_dinv[s] * g_dinv[d];
    float4 v = ((const float4*)(g_xw + (size_t)s * HH))[lane];
    float* p = g_agg + (size_t)d * HH + lane * 4;
    asm volatile("red.global.add.v4.f32 [%0], {%1, %2, %3, %4};"
                 :: "l"(p), "f"(coef * v.x), "f"(coef * v.y),
                    "f"(coef * v.z), "f"(coef * v.w)
                 : "memory");
}

// ---------------- BN(eval) + bias + ReLU: h = relu((agg + b - m)*scale + be) ----------------
__global__ void k_bnrelu(const float* __restrict__ b, const float* __restrict__ g,
                         const float* __restrict__ be, const float* __restrict__ m,
                         const float* __restrict__ v) {
    int i = blockIdx.x * blockDim.x + threadIdx.x;
    if (i < NN * HH) {
        int c = i & 127;
        float scale = g[c] * rsqrtf(v[c] + BN_EPS);
        float val = (g_agg[i] + b[c] - m[c]) * scale + be[c];
        g_h[i] = fmaxf(val, 0.f);
    }
}

// ---------------- per-edge MLP (factored): sigmoid(sum relu(A[s]+B[d]+b1)*W2 + b2) ----------------
__global__ void k_edge(const int* __restrict__ src, const int* __restrict__ dst,
                       const float* __restrict__ epb1, const float* __restrict__ epW2,
                       const float* __restrict__ epb2, float* __restrict__ out) {
    __shared__ __align__(16) float sb[HH];
    __shared__ __align__(16) float sw[HH];
    int t = threadIdx.x;
    if (t < 32) {
        ((float4*)sb)[t] = ((const float4*)epb1)[t];
        ((float4*)sw)[t] = ((const float4*)epW2)[t];
    }
    __syncthreads();
    int gt = blockIdx.x * blockDim.x + t;
    int e = gt >> 5;
    int lane = gt & 31;
    if (e >= EE) return;
    int s = src[e], d = dst[e];
    float4 a = ((const float4*)(g_A + (size_t)s * HH))[lane];
    float4 bb = ((const float4*)(g_B + (size_t)d * HH))[lane];
    float4 bi = ((const float4*)sb)[lane];
    float4 w = ((const float4*)sw)[lane];
    float p = fmaxf(a.x + bb.x + bi.x, 0.f) * w.x
            + fmaxf(a.y + bb.y + bi.y, 0.f) * w.y
            + fmaxf(a.z + bb.z + bi.z, 0.f) * w.z
            + fmaxf(a.w + bb.w + bi.w, 0.f) * w.w;
#pragma unroll
    for (int o = 16; o > 0; o >>= 1) p += __shfl_xor_sync(0xffffffffu, p, o);
    if (lane == 0) out[e] = 1.f / (1.f + __expf(-(p + epb2[0])));
}

// ---------------- launch ----------------
extern "C" void kernel_launch(void* const* d_in, const int* in_sizes, int n_in,
                              void* d_out, int out_size) {
    const float* x    = (const float*)d_in[0];
    const int*   ei   = (const int*)d_in[1];
    const int*   src  = ei;
    const int*   dst  = ei + EE;
    const float* W1   = (const float*)d_in[2];
    const float* b1   = (const float*)d_in[3];
    const float* g1   = (const float*)d_in[4];
    const float* be1  = (const float*)d_in[5];
    const float* m1   = (const float*)d_in[6];
    const float* v1   = (const float*)d_in[7];
    const float* W2   = (const float*)d_in[8];
    const float* b2   = (const float*)d_in[9];
    const float* g2   = (const float*)d_in[10];
    const float* be2  = (const float*)d_in[11];
    const float* m2   = (const float*)d_in[12];
    const float* v2   = (const float*)d_in[13];
    const float* epW1 = (const float*)d_in[14];
    const float* epb1 = (const float*)d_in[15];
    const float* epW2 = (const float*)d_in[16];
    const float* epb2 = (const float*)d_in[17];
    float* out = (float*)d_out;

    float *p_xw, *p_h, *p_A, *p_B;
    cudaGetSymbolAddress((void**)&p_xw, g_xw);
    cudaGetSymbolAddress((void**)&p_h,  g_h);
    cudaGetSymbolAddress((void**)&p_A,  g_A);
    cudaGetSymbolAddress((void**)&p_B,  g_B);

    const int TB = 256;
    dim3 gN((NN + TB - 1) / TB);
    dim3 gE((EE + TB - 1) / TB);
    dim3 gGemm((NN + 63) / 64);
    dim3 gSelf((NN * (HH / 4) + TB - 1) / TB);
    dim3 gScat(((size_t)EE * 32 + TB - 1) / TB);
    dim3 gBN(((size_t)NN * HH + TB - 1) / TB);

    // normalization coefficients
    k_deg_init<<<gN, TB>>>();
    k_deg_acc<<<gE, TB>>>(dst);
    k_dinv<<<gN, TB>>>();

    // layer 1
    k_gemm128<<<gGemm, TB>>>(x, W1, p_xw, NN);
    k_selfinit<<<gSelf, TB>>>();
    k_scatter<<<gScat, TB>>>(src, dst);
    k_bnrelu<<<gBN, TB>>>(b1, g1, be1, m1, v1);

    // layer 2
    k_gemm128<<<gGemm, TB>>>(p_h, W2, p_xw, NN);
    k_selfinit<<<gSelf, TB>>>();
    k_scatter<<<gScat, TB>>>(src, dst);
    k_bnrelu<<<gBN, TB>>>(b2, g2, be2, m2, v2);

    // factored edge predictor: A = h@epW1[:128], B = h@epW1[128:]
    k_gemm128<<<gGemm, TB>>>(p_h, epW1, p_A, NN);
    k_gemm128<<<gGemm, TB>>>(p_h, epW1 + 128 * 128, p_B, NN);
    k_edge<<<gScat, TB>>>(src, dst, epb1, epW2, epb2, out);
}

// round 14
// speedup vs baseline: 1.1529x; 1.1529x over previous
#include <cuda_runtime.h>
#include <cuda_bf16.h>
#include <math.h>

#define NN 50000
#define EE 800000
#define HH 128
#define BN_EPS 1e-5f

// Scratch (device globals; no allocation allowed)
__device__ int   g_cnt[NN];          // edge counts per dst
__device__ int   g_rowptr[NN + 1];   // CSR row pointers
__device__ int   g_cur[NN];          // scatter cursors
__device__ float g_dinv[NN];         // deg^-1/2 (deg includes self loop)
__device__ int   g_srt[EE];          // src sorted by dst
__device__ float g_coef[EE];         // dinv[src]*dinv[dst] per sorted edge
__device__ float g_xw[(size_t)NN * HH];   // GEMM output / messages
__device__ float g_h[(size_t)NN * HH];    // layer activations
__device__ float g_A[(size_t)NN * HH];    // h @ epW1[:H]
__device__ float g_B[(size_t)NN * HH];    // h @ epW1[H:]

// ---------------- histogram / CSR build ----------------
__global__ void k_clear() {
    int i = blockIdx.x * blockDim.x + threadIdx.x;
    if (i < NN) g_cnt[i] = 0;
}

__global__ void k_hist(const int* __restrict__ dst) {
    int e = blockIdx.x * blockDim.x + threadIdx.x;
    if (e < EE) atomicAdd(&g_cnt[dst[e]], 1);
}

// single block, 1024 threads: exclusive scan of g_cnt -> g_rowptr/g_cur; dinv from deg
__global__ void k_scan() {
    __shared__ int wsum[32];
    __shared__ int carry;
    int t = threadIdx.x, lane = t & 31, w = t >> 5;
    if (t == 0) carry = 0;
    __syncthreads();
    for (int base = 0; base < NN; base += 1024) {
        int i = base + t;
        int val = (i < NN) ? g_cnt[i] : 0;
        int sc = val;
#pragma unroll
        for (int off = 1; off < 32; off <<= 1) {
            int y = __shfl_up_sync(0xffffffffu, sc, off);
            if (lane >= off) sc += y;
        }
        if (lane == 31) wsum[w] = sc;
        __syncthreads();
        if (w == 0) {
            int x = wsum[lane];
            int s2 = x;
#pragma unroll
            for (int off = 1; off < 32; off <<= 1) {
                int y = __shfl_up_sync(0xffffffffu, s2, off);
                if (lane >= off) s2 += y;
            }
            wsum[lane] = s2 - x;  // exclusive warp offset
        }
        __syncthreads();
        int excl = carry + wsum[w] + (sc - val);
        if (i < NN) {
            g_rowptr[i] = excl;
            g_cur[i] = excl;
            g_dinv[i] = rsqrtf((float)val + 1.0f);  // +1 self loop
        }
        __syncthreads();
        if (t == 1023) carry += wsum[31] + sc;
        __syncthreads();
    }
    if (t == 0) g_rowptr[NN] = carry;
}

__global__ void k_sort(const int* __restrict__ src, const int* __restrict__ dst) {
    int e = blockIdx.x * blockDim.x + threadIdx.x;
    if (e >= EE) return;
    int s = src[e], d = dst[e];
    int pos = atomicAdd(&g_cur[d], 1);
    g_srt[pos] = s;
    g_coef[pos] = g_dinv[s] * g_dinv[d];
}

// ---------------- GEMM: Y[nrows,128] = X[nrows,128] @ W[128,128] ----------------
// 128-row tile, 256 threads, 16x4 register tile per thread.
__global__ __launch_bounds__(256) void k_gemm128(const float* __restrict__ X,
                                                 const float* __restrict__ W,
                                                 float* __restrict__ Y, int nrows) {
    __shared__ __align__(16) float sX[128][32];
    __shared__ __align__(16) float sW[32][128];
    int t = threadIdx.x;
    int r0 = blockIdx.x * 128;
    int cg = t & 31;   // cols cg*4 .. cg*4+3
    int rg = t >> 5;   // rows rg*16 .. rg*16+15

    float acc[16][4];
#pragma unroll
    for (int i = 0; i < 16; i++)
#pragma unroll
        for (int j = 0; j < 4; j++) acc[i][j] = 0.f;

    for (int kk = 0; kk < 128; kk += 32) {
#pragma unroll
        for (int p = 0; p < 16; p++) {  // 128*32/256 = 16
            int i = t + p * 256;
            int r = i >> 5, c = i & 31;
            int gr = r0 + r;
            sX[r][c] = (gr < nrows) ? __ldg(&X[(size_t)gr * 128 + kk + c]) : 0.f;
        }
#pragma unroll
        for (int p = 0; p < 16; p++) {  // 32*128/256 = 16
            int i = t + p * 256;
            int k = i >> 7, c = i & 127;
            sW[k][c] = __ldg(&W[(size_t)(kk + k) * 128 + c]);
        }
        __syncthreads();
#pragma unroll
        for (int k = 0; k < 32; k++) {
            float4 b = *(const float4*)&sW[k][cg * 4];
#pragma unroll
            for (int i = 0; i < 16; i++) {
                float a = sX[rg * 16 + i][k];
                acc[i][0] += a * b.x;
                acc[i][1] += a * b.y;
                acc[i][2] += a * b.z;
                acc[i][3] += a * b.w;
            }
        }
        __syncthreads();
    }
#pragma unroll
    for (int i = 0; i < 16; i++) {
        int gr = r0 + rg * 16 + i;
        if (gr < nrows) {
            float4 v = make_float4(acc[i][0], acc[i][1], acc[i][2], acc[i][3]);
            *(float4*)&Y[(size_t)gr * 128 + cg * 4] = v;
        }
    }
}

// ---------------- fused aggregate + bias + BN(eval) + ReLU ----------------
// One warp per node: h[n] = relu(bn(dinv[n]^2*xw[n] + sum coef*xw[src] + b))
__global__ __launch_bounds__(256) void k_aggbn(const float* __restrict__ b,
                                               const float* __restrict__ g,
                                               const float* __restrict__ be,
                                               const float* __restrict__ m,
                                               const float* __restrict__ v) {
    int gt = blockIdx.x * blockDim.x + threadIdx.x;
    int n = gt >> 5;
    int lane = gt & 31;
    if (n >= NN) return;
    const float4* xw4 = (const float4*)g_xw;

    float di = g_dinv[n];
    float c2 = di * di;
    float4 acc = xw4[(size_t)n * 32 + lane];
    acc.x *= c2; acc.y *= c2; acc.z *= c2; acc.w *= c2;

    int start = g_rowptr[n];
    int end = g_rowptr[n + 1];
    for (int base = start; base < end; base += 32) {
        int idx = base + lane;
        int s = 0; float cf = 0.f;
        if (idx < end) { s = g_srt[idx]; cf = g_coef[idx]; }
        int cnt = min(32, end - base);
        for (int j = 0; j < cnt; j++) {
            int sj = __shfl_sync(0xffffffffu, s, j);
            float cj = __shfl_sync(0xffffffffu, cf, j);
            float4 xv = xw4[(size_t)sj * 32 + lane];
            acc.x += cj * xv.x;
            acc.y += cj * xv.y;
            acc.z += cj * xv.z;
            acc.w += cj * xv.w;
        }
    }

    float4 bb = ((const float4*)b)[lane];
    float4 gg = ((const float4*)g)[lane];
    float4 bbe = ((const float4*)be)[lane];
    float4 mm = ((const float4*)m)[lane];
    float4 vv = ((const float4*)v)[lane];
    float4 o;
    o.x = fmaxf((acc.x + bb.x - mm.x) * (gg.x * rsqrtf(vv.x + BN_EPS)) + bbe.x, 0.f);
    o.y = fmaxf((acc.y + bb.y - mm.y) * (gg.y * rsqrtf(vv.y + BN_EPS)) + bbe.y, 0.f);
    o.z = fmaxf((acc.z + bb.z - mm.z) * (gg.z * rsqrtf(vv.z + BN_EPS)) + bbe.z, 0.f);
    o.w = fmaxf((acc.w + bb.w - mm.w) * (gg.w * rsqrtf(vv.w + BN_EPS)) + bbe.w, 0.f);
    ((float4*)g_h)[(size_t)n * 32 + lane] = o;
}

// ---------------- per-edge MLP (factored) ----------------
__global__ __launch_bounds__(256) void k_edge(const int* __restrict__ src,
                                              const int* __restrict__ dst,
                                              const float* __restrict__ epb1,
                                              const float* __restrict__ epW2,
                                              const float* __restrict__ epb2,
                                              float* __restrict__ out) {
    __shared__ __align__(16) float sb[HH];
    __shared__ __align__(16) float sw[HH];
    int t = threadIdx.x;
    if (t < 32) {
        ((float4*)sb)[t] = ((const float4*)epb1)[t];
        ((float4*)sw)[t] = ((const float4*)epW2)[t];
    }
    __syncthreads();
    int gt = blockIdx.x * blockDim.x + t;
    int e = gt >> 5;
    int lane = gt & 31;
    if (e >= EE) return;
    int s = src[e], d = dst[e];
    float4 a = ((const float4*)(g_A + (size_t)s * HH))[lane];
    float4 bb = ((const float4*)(g_B + (size_t)d * HH))[lane];
    float4 bi = ((const float4*)sb)[lane];
    float4 w = ((const float4*)sw)[lane];
    float p = fmaxf(a.x + bb.x + bi.x, 0.f) * w.x
            + fmaxf(a.y + bb.y + bi.y, 0.f) * w.y
            + fmaxf(a.z + bb.z + bi.z, 0.f) * w.z
            + fmaxf(a.w + bb.w + bi.w, 0.f) * w.w;
#pragma unroll
    for (int o = 16; o > 0; o >>= 1) p += __shfl_xor_sync(0xffffffffu, p, o);
    if (lane == 0) out[e] = 1.f / (1.f + __expf(-(p + epb2[0])));
}

// ---------------- launch ----------------
extern "C" void kernel_launch(void* const* d_in, const int* in_sizes, int n_in,
                              void* d_out, int out_size) {
    const float* x    = (const float*)d_in[0];
    const int*   ei   = (const int*)d_in[1];
    const int*   src  = ei;
    const int*   dst  = ei + EE;
    const float* W1   = (const float*)d_in[2];
    const float* b1   = (const float*)d_in[3];
    const float* g1   = (const float*)d_in[4];
    const float* be1  = (const float*)d_in[5];
    const float* m1   = (const float*)d_in[6];
    const float* v1   = (const float*)d_in[7];
    const float* W2   = (const float*)d_in[8];
    const float* b2   = (const float*)d_in[9];
    const float* g2   = (const float*)d_in[10];
    const float* be2  = (const float*)d_in[11];
    const float* m2   = (const float*)d_in[12];
    const float* v2   = (const float*)d_in[13];
    const float* epW1 = (const float*)d_in[14];
    const float* epb1 = (const float*)d_in[15];
    const float* epW2 = (const float*)d_in[16];
    const float* epb2 = (const float*)d_in[17];
    float* out = (float*)d_out;

    float *p_xw, *p_h, *p_A, *p_B;
    cudaGetSymbolAddress((void**)&p_xw, g_xw);
    cudaGetSymbolAddress((void**)&p_h,  g_h);
    cudaGetSymbolAddress((void**)&p_A,  g_A);
    cudaGetSymbolAddress((void**)&p_B,  g_B);

    const int TB = 256;
    dim3 gN((NN + TB - 1) / TB);
    dim3 gE((EE + TB - 1) / TB);
    dim3 gGemm((NN + 127) / 128);
    dim3 gWarpN(((size_t)NN * 32 + TB - 1) / TB);
    dim3 gWarpE(((size_t)EE * 32 + TB - 1) / TB);

    // CSR build (dst-sorted edges) + normalization coefficients
    k_clear<<<gN, TB>>>();
    k_hist<<<gE, TB>>>(dst);
    k_scan<<<1, 1024>>>();
    k_sort<<<gE, TB>>>(src, dst);

    // layer 1: GEMM -> fused aggregate+BN+ReLU
    k_gemm128<<<gGemm, TB>>>(x, W1, p_xw, NN);
    k_aggbn<<<gWarpN, TB>>>(b1, g1, be1, m1, v1);

    // layer 2
    k_gemm128<<<gGemm, TB>>>(p_h, W2, p_xw, NN);
    k_aggbn<<<gWarpN, TB>>>(b2, g2, be2, m2, v2);

    // factored edge predictor: A = h@epW1[:128], B = h@epW1[128:]
    k_gemm128<<<gGemm, TB>>>(p_h, epW1, p_A, NN);
    k_gemm128<<<gGemm, TB>>>(p_h, epW1 + 128 * 128, p_B, NN);
    k_edge<<<gWarpE, TB>>>(src, dst, epb1, epW2, epb2, out);
}

// round 15
// speedup vs baseline: 1.1876x; 1.0301x over previous
#include <cuda_runtime.h>
#include <cuda_bf16.h>
#include <math.h>

#define NN 50000
#define EE 800000
#define HH 128
#define BN_EPS 1e-5f
#define NB ((NN + 1023) / 1024)   // 49 scan blocks

// Scratch (device globals; no allocation allowed)
__device__ int   g_cnt[NN];          // edge counts per dst
__device__ int   g_rowptr[NN + 1];   // CSR row pointers
__device__ int   g_cur[NN];          // scatter cursors
__device__ int   g_bsum[64];         // per-block scan sums
__device__ int   g_boff[64];         // per-block scan offsets
__device__ float g_dinv[NN];         // deg^-1/2 (deg includes self loop)
__device__ int   g_srt[EE];          // src sorted by dst
__device__ float g_coef[EE];         // dinv[src]*dinv[dst] per sorted edge
__device__ float g_xw[(size_t)NN * HH];   // GEMM output / messages
__device__ float g_h[(size_t)NN * HH];    // layer activations
__device__ float g_A[(size_t)NN * HH];    // h @ epW1[:H]
__device__ float g_B[(size_t)NN * HH];    // h @ epW1[H:]

// ---------------- histogram / CSR build ----------------
__global__ void k_clear() {
    int i = blockIdx.x * blockDim.x + threadIdx.x;
    if (i < NN) g_cnt[i] = 0;
}

__global__ void k_hist(const int* __restrict__ dst) {
    int e = blockIdx.x * blockDim.x + threadIdx.x;
    if (e < EE) atomicAdd(&g_cnt[dst[e]], 1);
}

// two-level exclusive scan: per-block local scan + dinv
__global__ void k_scan1() {
    __shared__ int wsum[32];
    int t = threadIdx.x, lane = t & 31, w = t >> 5;
    int i = blockIdx.x * 1024 + t;
    int val = (i < NN) ? g_cnt[i] : 0;
    int sc = val;
#pragma unroll
    for (int off = 1; off < 32; off <<= 1) {
        int y = __shfl_up_sync(0xffffffffu, sc, off);
        if (lane >= off) sc += y;
    }
    if (lane == 31) wsum[w] = sc;
    __syncthreads();
    if (w == 0) {
        int x = wsum[lane];
        int s2 = x;
#pragma unroll
        for (int off = 1; off < 32; off <<= 1) {
            int y = __shfl_up_sync(0xffffffffu, s2, off);
            if (lane >= off) s2 += y;
        }
        wsum[lane] = s2 - x;  // exclusive warp offset
    }
    __syncthreads();
    int excl = wsum[w] + sc - val;  // block-local exclusive
    if (i < NN) {
        g_rowptr[i] = excl;
        g_dinv[i] = rsqrtf((float)val + 1.0f);  // +1 self loop
    }
    if (t == 1023) g_bsum[blockIdx.x] = excl + val;  // block total
}

// scan of block sums (tiny)
__global__ void k_scan2() {
    __shared__ int sv[64];
    int t = threadIdx.x;
    sv[t] = (t < NB) ? g_bsum[t] : 0;
    __syncthreads();
    if (t == 0) {
        int run = 0;
        for (int b = 0; b < NB; b++) { int x = sv[b]; sv[b] = run; run += x; }
        g_rowptr[NN] = run;
    }
    __syncthreads();
    if (t < NB) g_boff[t] = sv[t];
}

// add block offsets, init cursors
__global__ void k_scan3() {
    int i = blockIdx.x * blockDim.x + threadIdx.x;
    if (i < NN) {
        int v = g_rowptr[i] + g_boff[i >> 10];
        g_rowptr[i] = v;
        g_cur[i] = v;
    }
}

__global__ void k_sort(const int* __restrict__ src, const int* __restrict__ dst) {
    int e = blockIdx.x * blockDim.x + threadIdx.x;
    if (e >= EE) return;
    int s = src[e], d = dst[e];
    int pos = atomicAdd(&g_cur[d], 1);
    g_srt[pos] = s;
    g_coef[pos] = g_dinv[s] * g_dinv[d];
}

// ---------------- GEMM: Y[nrows,128] = X[nrows,128] @ W[128,128] ----------------
// 128-row tile, 256 threads, 16x4 register tile per thread.
// X tile stored k-major (sXT[k][row], stride 132 for 16B alignment) so the
// per-thread a-operands are 4 broadcast LDS.128 per k instead of 16 scalar LDS.
__global__ __launch_bounds__(256) void k_gemm128(const float* __restrict__ X,
                                                 const float* __restrict__ W,
                                                 float* __restrict__ Y, int nrows) {
    __shared__ __align__(16) float sXT[32][132];
    __shared__ __align__(16) float sW[32][132];
    int t = threadIdx.x;
    int r0 = blockIdx.x * 128;
    int cg = t & 31;   // cols cg*4 .. cg*4+3
    int rg = t >> 5;   // rows rg*16 .. rg*16+15

    float acc[16][4];
#pragma unroll
    for (int i = 0; i < 16; i++)
#pragma unroll
        for (int j = 0; j < 4; j++) acc[i][j] = 0.f;

    for (int kk = 0; kk < 128; kk += 32) {
#pragma unroll
        for (int p = 0; p < 16; p++) {  // 128 rows x 32 k / 256 thr = 16
            int i = t + p * 256;
            int r = i >> 5, c = i & 31;       // coalesced read of X row r
            int gr = r0 + r;
            sXT[c][r] = (gr < nrows) ? __ldg(&X[(size_t)gr * 128 + kk + c]) : 0.f;
        }
#pragma unroll
        for (int p = 0; p < 16; p++) {  // 32 k x 128 cols / 256 = 16
            int i = t + p * 256;
            int k = i >> 7, c = i & 127;
            sW[k][c] = __ldg(&W[(size_t)(kk + k) * 128 + c]);
        }
        __syncthreads();
#pragma unroll
        for (int k = 0; k < 32; k++) {
            float4 b = *(const float4*)&sW[k][cg * 4];
#pragma unroll
            for (int i4 = 0; i4 < 4; i4++) {
                float4 a = *(const float4*)&sXT[k][rg * 16 + i4 * 4];  // warp broadcast
                acc[i4 * 4 + 0][0] += a.x * b.x; acc[i4 * 4 + 0][1] += a.x * b.y;
                acc[i4 * 4 + 0][2] += a.x * b.z; acc[i4 * 4 + 0][3] += a.x * b.w;
                acc[i4 * 4 + 1][0] += a.y * b.x; acc[i4 * 4 + 1][1] += a.y * b.y;
                acc[i4 * 4 + 1][2] += a.y * b.z; acc[i4 * 4 + 1][3] += a.y * b.w;
                acc[i4 * 4 + 2][0] += a.z * b.x; acc[i4 * 4 + 2][1] += a.z * b.y;
                acc[i4 * 4 + 2][2] += a.z * b.z; acc[i4 * 4 + 2][3] += a.z * b.w;
                acc[i4 * 4 + 3][0] += a.w * b.x; acc[i4 * 4 + 3][1] += a.w * b.y;
                acc[i4 * 4 + 3][2] += a.w * b.z; acc[i4 * 4 + 3][3] += a.w * b.w;
            }
        }
        __syncthreads();
    }
#pragma unroll
    for (int i = 0; i < 16; i++) {
        int gr = r0 + rg * 16 + i;
        if (gr < nrows) {
            float4 v = make_float4(acc[i][0], acc[i][1], acc[i][2], acc[i][3]);
            *(float4*)&Y[(size_t)gr * 128 + cg * 4] = v;
        }
    }
}

// ---------------- fused aggregate + bias + BN(eval) + ReLU ----------------
// One warp per node: h[n] = relu(bn(dinv[n]^2*xw[n] + sum coef*xw[src] + b))
__global__ __launch_bounds__(256) void k_aggbn(const float* __restrict__ b,
                                               const float* __restrict__ g,
                                               const float* __restrict__ be,
                                               const float* __restrict__ m,
                                               const float* __restrict__ v) {
    int gt = blockIdx.x * blockDim.x + threadIdx.x;
    int n = gt >> 5;
    int lane = gt & 31;
    if (n >= NN) return;
    const float4* xw4 = (const float4*)g_xw;

    float di = g_dinv[n];
    float c2 = di * di;
    float4 acc = xw4[(size_t)n * 32 + lane];
    acc.x *= c2; acc.y *= c2; acc.z *= c2; acc.w *= c2;

    int start = g_rowptr[n];
    int end = g_rowptr[n + 1];
    for (int base = start; base < end; base += 32) {
        int idx = base + lane;
        int s = 0; float cf = 0.f;
        if (idx < end) { s = g_srt[idx]; cf = g_coef[idx]; }
        int cnt = min(32, end - base);
        for (int j = 0; j < cnt; j++) {
            int sj = __shfl_sync(0xffffffffu, s, j);
            float cj = __shfl_sync(0xffffffffu, cf, j);
            float4 xv = xw4[(size_t)sj * 32 + lane];
            acc.x += cj * xv.x;
            acc.y += cj * xv.y;
            acc.z += cj * xv.z;
            acc.w += cj * xv.w;
        }
    }

    float4 bb = ((const float4*)b)[lane];
    float4 gg = ((const float4*)g)[lane];
    float4 bbe = ((const float4*)be)[lane];
    float4 mm = ((const float4*)m)[lane];
    float4 vv = ((const float4*)v)[lane];
    float4 o;
    o.x = fmaxf((acc.x + bb.x - mm.x) * (gg.x * rsqrtf(vv.x + BN_EPS)) + bbe.x, 0.f);
    o.y = fmaxf((acc.y + bb.y - mm.y) * (gg.y * rsqrtf(vv.y + BN_EPS)) + bbe.y, 0.f);
    o.z = fmaxf((acc.z + bb.z - mm.z) * (gg.z * rsqrtf(vv.z + BN_EPS)) + bbe.z, 0.f);
    o.w = fmaxf((acc.w + bb.w - mm.w) * (gg.w * rsqrtf(vv.w + BN_EPS)) + bbe.w, 0.f);
    ((float4*)g_h)[(size_t)n * 32 + lane] = o;
}

// ---------------- per-edge MLP (factored) ----------------
__global__ __launch_bounds__(256) void k_edge(const int* __restrict__ src,
                                              const int* __restrict__ dst,
                                              const float* __restrict__ epb1,
                                              const float* __restrict__ epW2,
                                              const float* __restrict__ epb2,
                                              float* __restrict__ out) {
    __shared__ __align__(16) float sb[HH];
    __shared__ __align__(16) float sw[HH];
    int t = threadIdx.x;
    if (t < 32) {
        ((float4*)sb)[t] = ((const float4*)epb1)[t];
        ((float4*)sw)[t] = ((const float4*)epW2)[t];
    }
    __syncthreads();
    int gt = blockIdx.x * blockDim.x + t;
    int e = gt >> 5;
    int lane = gt & 31;
    if (e >= EE) return;
    int s = src[e], d = dst[e];
    float4 a = ((const float4*)(g_A + (size_t)s * HH))[lane];
    float4 bb = ((const float4*)(g_B + (size_t)d * HH))[lane];
    float4 bi = ((const float4*)sb)[lane];
    float4 w = ((const float4*)sw)[lane];
    float p = fmaxf(a.x + bb.x + bi.x, 0.f) * w.x
            + fmaxf(a.y + bb.y + bi.y, 0.f) * w.y
            + fmaxf(a.z + bb.z + bi.z, 0.f) * w.z
            + fmaxf(a.w + bb.w + bi.w, 0.f) * w.w;
#pragma unroll
    for (int o = 16; o > 0; o >>= 1) p += __shfl_xor_sync(0xffffffffu, p, o);
    if (lane == 0) out[e] = 1.f / (1.f + __expf(-(p + epb2[0])));
}

// ---------------- launch ----------------
extern "C" void kernel_launch(void* const* d_in, const int* in_sizes, int n_in,
                              void* d_out, int out_size) {
    const float* x    = (const float*)d_in[0];
    const int*   ei   = (const int*)d_in[1];
    const int*   src  = ei;
    const int*   dst  = ei + EE;
    const float* W1   = (const float*)d_in[2];
    const float* b1   = (const float*)d_in[3];
    const float* g1   = (const float*)d_in[4];
    const float* be1  = (const float*)d_in[5];
    const float* m1   = (const float*)d_in[6];
    const float* v1   = (const float*)d_in[7];
    const float* W2   = (const float*)d_in[8];
    const float* b2   = (const float*)d_in[9];
    const float* g2   = (const float*)d_in[10];
    const float* be2  = (const float*)d_in[11];
    const float* m2   = (const float*)d_in[12];
    const float* v2   = (const float*)d_in[13];
    const float* epW1 = (const float*)d_in[14];
    const float* epb1 = (const float*)d_in[15];
    const float* epW2 = (const float*)d_in[16];
    const float* epb2 = (const float*)d_in[17];
    float* out = (float*)d_out;

    float *p_xw, *p_h, *p_A, *p_B;
    cudaGetSymbolAddress((void**)&p_xw, g_xw);
    cudaGetSymbolAddress((void**)&p_h,  g_h);
    cudaGetSymbolAddress((void**)&p_A,  g_A);
    cudaGetSymbolAddress((void**)&p_B,  g_B);

    const int TB = 256;
    dim3 gN((NN + TB - 1) / TB);
    dim3 gE((EE + TB - 1) / TB);
    dim3 gGemm((NN + 127) / 128);
    dim3 gWarpN(((size_t)NN * 32 + TB - 1) / TB);
    dim3 gWarpE(((size_t)EE * 32 + TB - 1) / TB);

    // CSR build (dst-sorted edges) + normalization coefficients
    k_clear<<<gN, TB>>>();
    k_hist<<<gE, TB>>>(dst);
    k_scan1<<<NB, 1024>>>();
    k_scan2<<<1, 64>>>();
    k_scan3<<<gN, TB>>>();
    k_sort<<<gE, TB>>>(src, dst);

    // layer 1: GEMM -> fused aggregate+BN+ReLU
    k_gemm128<<<gGemm, TB>>>(x, W1, p_xw, NN);
    k_aggbn<<<gWarpN, TB>>>(b1, g1, be1, m1, v1);

    // layer 2
    k_gemm128<<<gGemm, TB>>>(p_h, W2, p_xw, NN);
    k_aggbn<<<gWarpN, TB>>>(b2, g2, be2, m2, v2);

    // factored edge predictor: A = h@epW1[:128], B = h@epW1[128:]
    k_gemm128<<<gGemm, TB>>>(p_h, epW1, p_A, NN);
    k_gemm128<<<gGemm, TB>>>(p_h, epW1 + 128 * 128, p_B, NN);
    k_edge<<<gWarpE, TB>>>(src, dst, epb1, epW2, epb2, out);
}